// round 1
// baseline (speedup 1.0000x reference)
#include <cuda_runtime.h>

#define BB 2
#define SS 2048
#define HH 16
#define DD 64
#define EE 1024
#define MM (BB*SS)        /* 4096 */
#define N3 (3*EE)         /* 3072 */
#define OUTN (MM*EE)      /* 4194304 */

// Scratch (allocation-free rule: __device__ globals)
__device__ float g_q[BB*HH*SS*DD];     // q in [B,H,S,D]
__device__ float g_attn[MM*EE];        // attention output, [B,S,E] row-major
__device__ float g_kscr[BB*HH*SS*DD];  // fallback if harness only wants `out`
__device__ float g_vscr[BB*HH*SS*DD];

// ---------------------------------------------------------------------------
// QKV GEMM: [4096,1024] x [1024,3072] + bias, scatter epilogue into
// q/k/v [B,H,S,D] layouts.
// ---------------------------------------------------------------------------
__global__ __launch_bounds__(256) void qkv_gemm_kernel(
    const float* __restrict__ A, const float* __restrict__ Bw,
    const float* __restrict__ bias,
    float* __restrict__ qb, float* __restrict__ kb, float* __restrict__ vb)
{
    __shared__ float As[16][132];   // [k][m], padded vs bank conflicts
    __shared__ float Bs[16][128];   // [k][n]

    const int tid = threadIdx.x;
    const int m0 = blockIdx.y * 128;
    const int n0 = blockIdx.x * 128;
    const int tx = tid & 15, ty = tid >> 4;

    const int aRow = tid >> 2;            // 0..63
    const int aCol = (tid & 3) << 2;      // 0,4,8,12
    const int bRow = tid >> 5;            // 0..7
    const int bCol = (tid & 31) << 2;     // 0..124

    float acc[8][8];
#pragma unroll
    for (int i = 0; i < 8; i++)
#pragma unroll
        for (int j = 0; j < 8; j++) acc[i][j] = 0.f;

    for (int k0 = 0; k0 < EE; k0 += 16) {
#pragma unroll
        for (int p = 0; p < 2; p++) {
            float4 a = *(const float4*)&A[(m0 + aRow + p*64)*EE + k0 + aCol];
            As[aCol+0][aRow + p*64] = a.x;
            As[aCol+1][aRow + p*64] = a.y;
            As[aCol+2][aRow + p*64] = a.z;
            As[aCol+3][aRow + p*64] = a.w;
        }
#pragma unroll
        for (int p = 0; p < 2; p++) {
            *(float4*)&Bs[bRow + p*8][bCol] =
                *(const float4*)&Bw[(k0 + bRow + p*8)*N3 + n0 + bCol];
        }
        __syncthreads();
#pragma unroll
        for (int kk = 0; kk < 16; kk++) {
            float af[8], bf[8];
            *(float4*)&af[0] = *(const float4*)&As[kk][ty*8];
            *(float4*)&af[4] = *(const float4*)&As[kk][ty*8 + 4];
            *(float4*)&bf[0] = *(const float4*)&Bs[kk][tx*8];
            *(float4*)&bf[4] = *(const float4*)&Bs[kk][tx*8 + 4];
#pragma unroll
            for (int i = 0; i < 8; i++)
#pragma unroll
                for (int j = 0; j < 8; j++) acc[i][j] += af[i]*bf[j];
        }
        __syncthreads();
    }

    // Epilogue: bias + scatter to q/k/v [B,H,S,D]
#pragma unroll
    for (int i = 0; i < 8; i++) {
        const int m = m0 + ty*8 + i;
        const int b = m >> 11;       // / 2048
        const int s = m & 2047;
#pragma unroll
        for (int j = 0; j < 8; j += 4) {
            const int n = n0 + tx*8 + j;
            float4 bias4 = *(const float4*)&bias[n];
            float4 v;
            v.x = acc[i][j+0] + bias4.x;
            v.y = acc[i][j+1] + bias4.y;
            v.z = acc[i][j+2] + bias4.z;
            v.w = acc[i][j+3] + bias4.w;
            const int seg = n >> 10;         // 0=q 1=k 2=v
            const int c   = n & 1023;
            const int h   = c >> 6;
            const int d   = c & 63;
            float* dst = (seg == 0) ? qb : ((seg == 1) ? kb : vb);
            *(float4*)&dst[(((b*HH) + h)*SS + s)*DD + d] = v;
        }
    }
}

// ---------------------------------------------------------------------------
// Flash attention fp32, causal. 64 queries per block, 128 threads.
// Thread layout: tid = ql*2 + half; thread owns dims [half*32, half*32+32).
// ---------------------------------------------------------------------------
__global__ __launch_bounds__(128) void attn_kernel(
    const float* __restrict__ Q, const float* __restrict__ K,
    const float* __restrict__ V, float* __restrict__ O)
{
    __shared__ float Ks[64][64];
    __shared__ float Vs[64][64];

    const int tid  = threadIdx.x;
    const int ql   = tid >> 1;
    const int half = tid & 1;
    const int qt = blockIdx.x, h = blockIdx.y, b = blockIdx.z;
    const int qg = qt*64 + ql;

    const float* Qb = Q + (size_t)(b*HH + h)*SS*DD;
    const float* Kb = K + (size_t)(b*HH + h)*SS*DD;
    const float* Vb = V + (size_t)(b*HH + h)*SS*DD;

    float4 qreg[8];
#pragma unroll
    for (int j = 0; j < 8; j++)
        qreg[j] = *(const float4*)&Qb[qg*DD + half*32 + j*4];

    float4 acc[8];
#pragma unroll
    for (int j = 0; j < 8; j++) acc[j] = make_float4(0.f, 0.f, 0.f, 0.f);
    float m_i = -1e30f, l_i = 0.f;
    const float scale = 0.125f;   // 1/sqrt(64)

    for (int kt = 0; kt <= qt; kt++) {
        __syncthreads();
#pragma unroll
        for (int r = 0; r < 8; r++) {
            const int idx = r*128 + tid;       // 0..1023
            const int row = idx >> 4;
            const int c4  = (idx & 15) << 2;
            *(float4*)&Ks[row][c4] = *(const float4*)&Kb[(kt*64 + row)*DD + c4];
            *(float4*)&Vs[row][c4] = *(const float4*)&Vb[(kt*64 + row)*DD + c4];
        }
        __syncthreads();

        // --- scores ---
        float sreg[32];
        float rowmax = m_i;
#pragma unroll
        for (int k = 0; k < 64; k++) {
            float part = 0.f;
#pragma unroll
            for (int j = 0; j < 8; j++) {
                float4 kk4 = *(const float4*)&Ks[k][half*32 + j*4];
                part += qreg[j].x*kk4.x + qreg[j].y*kk4.y
                      + qreg[j].z*kk4.z + qreg[j].w*kk4.w;
            }
            float full = part + __shfl_xor_sync(0xffffffffu, part, 1);
            float sc = full * scale;
            if (kt*64 + k > qg) sc = -1e30f;
            if ((k >> 5) == half) sreg[k & 31] = sc;
            rowmax = fmaxf(rowmax, sc);
        }

        // --- online softmax ---
        const float m_new  = rowmax;
        const float alphaf = __expf(m_i - m_new);
        float lsum = 0.f;
#pragma unroll
        for (int i = 0; i < 32; i++) {
            sreg[i] = __expf(sreg[i] - m_new);   // reuse sreg as p
            lsum += sreg[i];
        }
        lsum += __shfl_xor_sync(0xffffffffu, lsum, 1);
        l_i = l_i * alphaf + lsum;
        m_i = m_new;
#pragma unroll
        for (int j = 0; j < 8; j++) {
            acc[j].x *= alphaf; acc[j].y *= alphaf;
            acc[j].z *= alphaf; acc[j].w *= alphaf;
        }

        // --- accumulate p * V ---
#pragma unroll
        for (int i = 0; i < 32; i++) {
            const float pA = sreg[i];
            const float pB = __shfl_xor_sync(0xffffffffu, pA, 1);
            const int kA = half*32 + i;
            const int kB = (1 - half)*32 + i;
#pragma unroll
            for (int j = 0; j < 8; j++) {
                float4 vA = *(const float4*)&Vs[kA][half*32 + j*4];
                float4 vB = *(const float4*)&Vs[kB][half*32 + j*4];
                acc[j].x += pA*vA.x; acc[j].y += pA*vA.y;
                acc[j].z += pA*vA.z; acc[j].w += pA*vA.w;
                acc[j].x += pB*vB.x; acc[j].y += pB*vB.y;
                acc[j].z += pB*vB.z; acc[j].w += pB*vB.w;
            }
        }
    }

    // write [B,S,E] row-major for the proj GEMM
    const float inv = 1.f / l_i;
    const int row = b*SS + qg;
#pragma unroll
    for (int j = 0; j < 8; j++) {
        float4 o;
        o.x = acc[j].x*inv; o.y = acc[j].y*inv;
        o.z = acc[j].z*inv; o.w = acc[j].w*inv;
        *(float4*)&O[(size_t)row*EE + h*64 + half*32 + j*4] = o;
    }
}

// ---------------------------------------------------------------------------
// Proj GEMM: [4096,1024] x [1024,1024] + bias -> out
// ---------------------------------------------------------------------------
__global__ __launch_bounds__(256) void proj_gemm_kernel(
    const float* __restrict__ A, const float* __restrict__ Bw,
    const float* __restrict__ bias, float* __restrict__ C)
{
    __shared__ float As[16][132];
    __shared__ float Bs[16][128];

    const int tid = threadIdx.x;
    const int m0 = blockIdx.y * 128;
    const int n0 = blockIdx.x * 128;
    const int tx = tid & 15, ty = tid >> 4;

    const int aRow = tid >> 2;
    const int aCol = (tid & 3) << 2;
    const int bRow = tid >> 5;
    const int bCol = (tid & 31) << 2;

    float acc[8][8];
#pragma unroll
    for (int i = 0; i < 8; i++)
#pragma unroll
        for (int j = 0; j < 8; j++) acc[i][j] = 0.f;

    for (int k0 = 0; k0 < EE; k0 += 16) {
#pragma unroll
        for (int p = 0; p < 2; p++) {
            float4 a = *(const float4*)&A[(m0 + aRow + p*64)*EE + k0 + aCol];
            As[aCol+0][aRow + p*64] = a.x;
            As[aCol+1][aRow + p*64] = a.y;
            As[aCol+2][aRow + p*64] = a.z;
            As[aCol+3][aRow + p*64] = a.w;
        }
#pragma unroll
        for (int p = 0; p < 2; p++) {
            *(float4*)&Bs[bRow + p*8][bCol] =
                *(const float4*)&Bw[(k0 + bRow + p*8)*EE + n0 + bCol];
        }
        __syncthreads();
#pragma unroll
        for (int kk = 0; kk < 16; kk++) {
            float af[8], bf[8];
            *(float4*)&af[0] = *(const float4*)&As[kk][ty*8];
            *(float4*)&af[4] = *(const float4*)&As[kk][ty*8 + 4];
            *(float4*)&bf[0] = *(const float4*)&Bs[kk][tx*8];
            *(float4*)&bf[4] = *(const float4*)&Bs[kk][tx*8 + 4];
#pragma unroll
            for (int i = 0; i < 8; i++)
#pragma unroll
                for (int j = 0; j < 8; j++) acc[i][j] += af[i]*bf[j];
        }
        __syncthreads();
    }

#pragma unroll
    for (int i = 0; i < 8; i++) {
        const int m = m0 + ty*8 + i;
#pragma unroll
        for (int j = 0; j < 8; j += 4) {
            const int n = n0 + tx*8 + j;
            float4 bias4 = *(const float4*)&bias[n];
            float4 v;
            v.x = acc[i][j+0] + bias4.x;
            v.y = acc[i][j+1] + bias4.y;
            v.z = acc[i][j+2] + bias4.z;
            v.w = acc[i][j+3] + bias4.w;
            *(float4*)&C[(size_t)m*EE + n] = v;
        }
    }
}

// ---------------------------------------------------------------------------
extern "C" void kernel_launch(void* const* d_in, const int* in_sizes, int n_in,
                              void* d_out, int out_size)
{
    const float* x      = (const float*)d_in[0];
    const float* qkv_w  = (const float*)d_in[1];
    const float* qkv_b  = (const float*)d_in[2];
    const float* proj_w = (const float*)d_in[3];
    const float* proj_b = (const float*)d_in[4];
    float* out = (float*)d_out;

    float *qbuf, *attnbuf, *kscr, *vscr;
    cudaGetSymbolAddress((void**)&qbuf,    g_q);
    cudaGetSymbolAddress((void**)&attnbuf, g_attn);
    cudaGetSymbolAddress((void**)&kscr,    g_kscr);
    cudaGetSymbolAddress((void**)&vscr,    g_vscr);

    // Reference returns (out, k, v): if the harness buffer holds all three,
    // write k/v straight into d_out; otherwise keep them in scratch.
    const bool kv_in_out = (out_size >= 3*OUTN);
    float* kdst = kv_in_out ? (out + OUTN)   : kscr;
    float* vdst = kv_in_out ? (out + 2*OUTN) : vscr;

    qkv_gemm_kernel<<<dim3(N3/128, MM/128), 256>>>(x, qkv_w, qkv_b,
                                                   qbuf, kdst, vdst);
    attn_kernel<<<dim3(SS/64, HH, BB), 128>>>(qbuf, kdst, vdst, attnbuf);
    proj_gemm_kernel<<<dim3(EE/128, MM/128), 256>>>(attnbuf, proj_w, proj_b, out);
}

// round 2
// speedup vs baseline: 1.3638x; 1.3638x over previous
#include <cuda_runtime.h>
#include <cstdint>

#define BB 2
#define SS 2048
#define HH 16
#define DD 64
#define EE 1024
#define MM (BB*SS)        /* 4096 */
#define N3 (3*EE)         /* 3072 */
#define OUTN (MM*EE)      /* 4194304 */

// Scratch (allocation-free rule: __device__ globals)
__device__ float g_q[BB*HH*SS*DD];     // q in [B,H,S,D]
__device__ float g_attn[MM*EE];        // attention output, [B,S,E] row-major
__device__ float g_kscr[BB*HH*SS*DD];  // fallback if harness only wants `out`
__device__ float g_vscr[BB*HH*SS*DD];

__device__ __forceinline__ uint32_t f2tf32(float f) {
    uint32_t r;
    asm("cvt.rna.tf32.f32 %0, %1;" : "=r"(r) : "f"(f));
    return r;
}

__device__ __forceinline__ void mma_tf32(float c[4], const uint32_t a[4], const uint32_t b[2]) {
    asm volatile(
        "mma.sync.aligned.m16n8k8.row.col.f32.tf32.tf32.f32 "
        "{%0,%1,%2,%3}, {%4,%5,%6,%7}, {%8,%9}, {%0,%1,%2,%3};"
        : "+f"(c[0]), "+f"(c[1]), "+f"(c[2]), "+f"(c[3])
        : "r"(a[0]), "r"(a[1]), "r"(a[2]), "r"(a[3]), "r"(b[0]), "r"(b[1]));
}

// ---------------------------------------------------------------------------
// tf32 tensor-core GEMM: C[M,NDIM] = A[M,1024] * B[1024,NDIM] + bias
// Block tile 128x128, K-step 32, 256 threads (8 warps, 4x2 warp grid),
// warp tile 32x64 (2x8 m16n8k8 frags). EPI=1: QKV scatter epilogue.
// ---------------------------------------------------------------------------
template<int NDIM, int EPI>
__global__ __launch_bounds__(256, 1) void mma_gemm_kernel(
    const float* __restrict__ A, const float* __restrict__ Bw,
    const float* __restrict__ bias,
    float* __restrict__ out0, float* __restrict__ out1, float* __restrict__ out2)
{
    __shared__ uint32_t As[128][36];   // [m][k], stride 36 -> conflict-free frag LDS
    __shared__ uint32_t Bs[32][132];   // [k][n], stride 132 -> conflict-free frag LDS

    const int tid  = threadIdx.x;
    const int lane = tid & 31;
    const int warp = tid >> 5;
    const int wm   = warp & 3;         // 0..3 -> m offset wm*32
    const int wn   = warp >> 2;        // 0..1 -> n offset wn*64
    const int m0   = blockIdx.y * 128;
    const int n0   = blockIdx.x * 128;
    const int lq   = lane >> 2;        // group id 0..7
    const int lr   = lane & 3;         // thread-in-group 0..3

    float acc[2][8][4];
#pragma unroll
    for (int i = 0; i < 2; i++)
#pragma unroll
        for (int j = 0; j < 8; j++)
#pragma unroll
            for (int t = 0; t < 4; t++) acc[i][j][t] = 0.f;

    // global-load assignments (4 float4 each for A and B per K-tile)
    float4 pa[4], pb[4];
#pragma unroll
    for (int i = 0; i < 4; i++) {
        const int idx = i * 256 + tid;
        const int am  = idx >> 3, ak4 = (idx & 7) << 2;
        const int bk  = idx >> 5, bn4 = (idx & 31) << 2;
        pa[i] = *(const float4*)&A[(size_t)(m0 + am) * EE + ak4];
        pb[i] = *(const float4*)&Bw[(size_t)bk * NDIM + n0 + bn4];
    }

    for (int k0 = 0; k0 < EE; k0 += 32) {
        // stage regs -> smem (with tf32 convert)
#pragma unroll
        for (int i = 0; i < 4; i++) {
            const int idx = i * 256 + tid;
            const int am  = idx >> 3, ak4 = (idx & 7) << 2;
            const int bk  = idx >> 5, bn4 = (idx & 31) << 2;
            uint4 ua = make_uint4(f2tf32(pa[i].x), f2tf32(pa[i].y),
                                  f2tf32(pa[i].z), f2tf32(pa[i].w));
            uint4 ub = make_uint4(f2tf32(pb[i].x), f2tf32(pb[i].y),
                                  f2tf32(pb[i].z), f2tf32(pb[i].w));
            *(uint4*)&As[am][ak4] = ua;
            *(uint4*)&Bs[bk][bn4] = ub;
        }
        __syncthreads();

        // prefetch next K-tile while computing
        if (k0 + 32 < EE) {
#pragma unroll
            for (int i = 0; i < 4; i++) {
                const int idx = i * 256 + tid;
                const int am  = idx >> 3, ak4 = (idx & 7) << 2;
                const int bk  = idx >> 5, bn4 = (idx & 31) << 2;
                pa[i] = *(const float4*)&A[(size_t)(m0 + am) * EE + k0 + 32 + ak4];
                pb[i] = *(const float4*)&Bw[(size_t)(k0 + 32 + bk) * NDIM + n0 + bn4];
            }
        }

#pragma unroll
        for (int kk = 0; kk < 32; kk += 8) {
            uint32_t af[2][4], bf[8][2];
#pragma unroll
            for (int mt = 0; mt < 2; mt++) {
                const int row = wm * 32 + mt * 16 + lq;
                af[mt][0] = As[row][kk + lr];
                af[mt][1] = As[row + 8][kk + lr];
                af[mt][2] = As[row][kk + lr + 4];
                af[mt][3] = As[row + 8][kk + lr + 4];
            }
#pragma unroll
            for (int nt = 0; nt < 8; nt++) {
                const int col = wn * 64 + nt * 8 + lq;
                bf[nt][0] = Bs[kk + lr][col];
                bf[nt][1] = Bs[kk + lr + 4][col];
            }
#pragma unroll
            for (int mt = 0; mt < 2; mt++)
#pragma unroll
                for (int nt = 0; nt < 8; nt++)
                    mma_tf32(acc[mt][nt], af[mt], bf[nt]);
        }
        __syncthreads();
    }

    // epilogue
#pragma unroll
    for (int mt = 0; mt < 2; mt++) {
        const int mA = m0 + wm * 32 + mt * 16 + lq;
        const int mB = mA + 8;
#pragma unroll
        for (int nt = 0; nt < 8; nt++) {
            const int n  = n0 + wn * 64 + nt * 8 + 2 * lr;
            const float bs0 = bias[n], bs1 = bias[n + 1];
            float2 vA = make_float2(acc[mt][nt][0] + bs0, acc[mt][nt][1] + bs1);
            float2 vB = make_float2(acc[mt][nt][2] + bs0, acc[mt][nt][3] + bs1);
            if (EPI == 0) {
                *(float2*)&out0[(size_t)mA * NDIM + n] = vA;
                *(float2*)&out0[(size_t)mB * NDIM + n] = vB;
            } else {
                const int seg = n >> 10;          // 0=q 1=k 2=v
                const int c   = n & 1023;
                const int h   = c >> 6;
                const int d   = c & 63;
                float* dst = (seg == 0) ? out0 : ((seg == 1) ? out1 : out2);
                const int bA = mA >> 11, sA = mA & 2047;
                const int bB = mB >> 11, sB = mB & 2047;
                *(float2*)&dst[(((size_t)(bA * HH) + h) * SS + sA) * DD + d] = vA;
                *(float2*)&dst[(((size_t)(bB * HH) + h) * SS + sB) * DD + d] = vB;
            }
        }
    }
}

// ---------------------------------------------------------------------------
// Flash attention fp32, causal. 64 queries per block, 128 threads.
// (unchanged from Round-1 passing kernel)
// ---------------------------------------------------------------------------
__global__ __launch_bounds__(128) void attn_kernel(
    const float* __restrict__ Q, const float* __restrict__ K,
    const float* __restrict__ V, float* __restrict__ O)
{
    __shared__ float Ks[64][64];
    __shared__ float Vs[64][64];

    const int tid  = threadIdx.x;
    const int ql   = tid >> 1;
    const int half = tid & 1;
    const int qt = blockIdx.x, h = blockIdx.y, b = blockIdx.z;
    const int qg = qt*64 + ql;

    const float* Qb = Q + (size_t)(b*HH + h)*SS*DD;
    const float* Kb = K + (size_t)(b*HH + h)*SS*DD;
    const float* Vb = V + (size_t)(b*HH + h)*SS*DD;

    float4 qreg[8];
#pragma unroll
    for (int j = 0; j < 8; j++)
        qreg[j] = *(const float4*)&Qb[qg*DD + half*32 + j*4];

    float4 acc[8];
#pragma unroll
    for (int j = 0; j < 8; j++) acc[j] = make_float4(0.f, 0.f, 0.f, 0.f);
    float m_i = -1e30f, l_i = 0.f;
    const float scale = 0.125f;   // 1/sqrt(64)

    for (int kt = 0; kt <= qt; kt++) {
        __syncthreads();
#pragma unroll
        for (int r = 0; r < 8; r++) {
            const int idx = r*128 + tid;       // 0..1023
            const int row = idx >> 4;
            const int c4  = (idx & 15) << 2;
            *(float4*)&Ks[row][c4] = *(const float4*)&Kb[(kt*64 + row)*DD + c4];
            *(float4*)&Vs[row][c4] = *(const float4*)&Vb[(kt*64 + row)*DD + c4];
        }
        __syncthreads();

        // --- scores ---
        float sreg[32];
        float rowmax = m_i;
#pragma unroll
        for (int k = 0; k < 64; k++) {
            float part = 0.f;
#pragma unroll
            for (int j = 0; j < 8; j++) {
                float4 kk4 = *(const float4*)&Ks[k][half*32 + j*4];
                part += qreg[j].x*kk4.x + qreg[j].y*kk4.y
                      + qreg[j].z*kk4.z + qreg[j].w*kk4.w;
            }
            float full = part + __shfl_xor_sync(0xffffffffu, part, 1);
            float sc = full * scale;
            if (kt*64 + k > qg) sc = -1e30f;
            if ((k >> 5) == half) sreg[k & 31] = sc;
            rowmax = fmaxf(rowmax, sc);
        }

        // --- online softmax ---
        const float m_new  = rowmax;
        const float alphaf = __expf(m_i - m_new);
        float lsum = 0.f;
#pragma unroll
        for (int i = 0; i < 32; i++) {
            sreg[i] = __expf(sreg[i] - m_new);   // reuse sreg as p
            lsum += sreg[i];
        }
        lsum += __shfl_xor_sync(0xffffffffu, lsum, 1);
        l_i = l_i * alphaf + lsum;
        m_i = m_new;
#pragma unroll
        for (int j = 0; j < 8; j++) {
            acc[j].x *= alphaf; acc[j].y *= alphaf;
            acc[j].z *= alphaf; acc[j].w *= alphaf;
        }

        // --- accumulate p * V ---
#pragma unroll
        for (int i = 0; i < 32; i++) {
            const float pA = sreg[i];
            const float pB = __shfl_xor_sync(0xffffffffu, pA, 1);
            const int kA = half*32 + i;
            const int kB = (1 - half)*32 + i;
#pragma unroll
            for (int j = 0; j < 8; j++) {
                float4 vA = *(const float4*)&Vs[kA][half*32 + j*4];
                float4 vB = *(const float4*)&Vs[kB][half*32 + j*4];
                acc[j].x += pA*vA.x; acc[j].y += pA*vA.y;
                acc[j].z += pA*vA.z; acc[j].w += pA*vA.w;
                acc[j].x += pB*vB.x; acc[j].y += pB*vB.y;
                acc[j].z += pB*vB.z; acc[j].w += pB*vB.w;
            }
        }
    }

    // write [B,S,E] row-major for the proj GEMM
    const float inv = 1.f / l_i;
    const int row = b*SS + qg;
#pragma unroll
    for (int j = 0; j < 8; j++) {
        float4 o;
        o.x = acc[j].x*inv; o.y = acc[j].y*inv;
        o.z = acc[j].z*inv; o.w = acc[j].w*inv;
        *(float4*)&O[(size_t)row*EE + h*64 + half*32 + j*4] = o;
    }
}

// ---------------------------------------------------------------------------
extern "C" void kernel_launch(void* const* d_in, const int* in_sizes, int n_in,
                              void* d_out, int out_size)
{
    const float* x      = (const float*)d_in[0];
    const float* qkv_w  = (const float*)d_in[1];
    const float* qkv_b  = (const float*)d_in[2];
    const float* proj_w = (const float*)d_in[3];
    const float* proj_b = (const float*)d_in[4];
    float* out = (float*)d_out;

    float *qbuf, *attnbuf, *kscr, *vscr;
    cudaGetSymbolAddress((void**)&qbuf,    g_q);
    cudaGetSymbolAddress((void**)&attnbuf, g_attn);
    cudaGetSymbolAddress((void**)&kscr,    g_kscr);
    cudaGetSymbolAddress((void**)&vscr,    g_vscr);

    // Reference returns (out, k, v): if the harness buffer holds all three,
    // write k/v straight into d_out; otherwise keep them in scratch.
    const bool kv_in_out = (out_size >= 3*OUTN);
    float* kdst = kv_in_out ? (out + OUTN)   : kscr;
    float* vdst = kv_in_out ? (out + 2*OUTN) : vscr;

    mma_gemm_kernel<N3, 1><<<dim3(N3/128, MM/128), 256>>>(x, qkv_w, qkv_b,
                                                          qbuf, kdst, vdst);
    attn_kernel<<<dim3(SS/64, HH, BB), 128>>>(qbuf, kdst, vdst, attnbuf);
    mma_gemm_kernel<EE, 0><<<dim3(EE/128, MM/128), 256>>>(attnbuf, proj_w, proj_b,
                                                          out, nullptr, nullptr);
}

// round 6
// speedup vs baseline: 4.1234x; 3.0235x over previous
#include <cuda_runtime.h>
#include <cstdint>

#define BB 2
#define SS 2048
#define HH 16
#define DD 64
#define EE 1024
#define MM (BB*SS)        /* 4096 */
#define N3 (3*EE)         /* 3072 */
#define OUTN (MM*EE)      /* 4194304 */

// Scratch (allocation-free rule: __device__ globals)
__device__ float g_q[BB*HH*SS*DD];     // q in [B,H,S,D]
__device__ float g_attn[MM*EE];        // attention output, [B,S,E] row-major
__device__ float g_kscr[BB*HH*SS*DD];  // fallback if harness only wants `out`
__device__ float g_vscr[BB*HH*SS*DD];

__device__ __forceinline__ uint32_t f2tf32(float f) {
    uint32_t r;
    asm("cvt.rna.tf32.f32 %0, %1;" : "=r"(r) : "f"(f));
    return r;
}

__device__ __forceinline__ void mma_tf32(float c[4], const uint32_t a[4], const uint32_t b[2]) {
    asm volatile(
        "mma.sync.aligned.m16n8k8.row.col.f32.tf32.tf32.f32 "
        "{%0,%1,%2,%3}, {%4,%5,%6,%7}, {%8,%9}, {%0,%1,%2,%3};"
        : "+f"(c[0]), "+f"(c[1]), "+f"(c[2]), "+f"(c[3])
        : "r"(a[0]), "r"(a[1]), "r"(a[2]), "r"(a[3]), "r"(b[0]), "r"(b[1]));
}

// ---------------------------------------------------------------------------
// tf32 tensor-core GEMM: C[M,NDIM] = A[M,1024] * B[1024,NDIM] + bias
// Block tile 128x128, K-step 32, 256 threads (8 warps, 4x2 warp grid),
// warp tile 32x64 (2x8 m16n8k8 frags). EPI=1: QKV scatter epilogue.
// ---------------------------------------------------------------------------
template<int NDIM, int EPI>
__global__ __launch_bounds__(256, 1) void mma_gemm_kernel(
    const float* __restrict__ A, const float* __restrict__ Bw,
    const float* __restrict__ bias,
    float* __restrict__ out0, float* __restrict__ out1, float* __restrict__ out2)
{
    __shared__ uint32_t As[128][36];   // [m][k]
    __shared__ uint32_t Bs[32][132];   // [k][n]

    const int tid  = threadIdx.x;
    const int lane = tid & 31;
    const int warp = tid >> 5;
    const int wm   = warp & 3;
    const int wn   = warp >> 2;
    const int m0   = blockIdx.y * 128;
    const int n0   = blockIdx.x * 128;
    const int lq   = lane >> 2;
    const int lr   = lane & 3;

    float acc[2][8][4];
#pragma unroll
    for (int i = 0; i < 2; i++)
#pragma unroll
        for (int j = 0; j < 8; j++)
#pragma unroll
            for (int t = 0; t < 4; t++) acc[i][j][t] = 0.f;

    float4 pa[4], pb[4];
#pragma unroll
    for (int i = 0; i < 4; i++) {
        const int idx = i * 256 + tid;
        const int am  = idx >> 3, ak4 = (idx & 7) << 2;
        const int bk  = idx >> 5, bn4 = (idx & 31) << 2;
        pa[i] = *(const float4*)&A[(size_t)(m0 + am) * EE + ak4];
        pb[i] = *(const float4*)&Bw[(size_t)bk * NDIM + n0 + bn4];
    }

    for (int k0 = 0; k0 < EE; k0 += 32) {
#pragma unroll
        for (int i = 0; i < 4; i++) {
            const int idx = i * 256 + tid;
            const int am  = idx >> 3, ak4 = (idx & 7) << 2;
            const int bk  = idx >> 5, bn4 = (idx & 31) << 2;
            uint4 ua = make_uint4(f2tf32(pa[i].x), f2tf32(pa[i].y),
                                  f2tf32(pa[i].z), f2tf32(pa[i].w));
            uint4 ub = make_uint4(f2tf32(pb[i].x), f2tf32(pb[i].y),
                                  f2tf32(pb[i].z), f2tf32(pb[i].w));
            *(uint4*)&As[am][ak4] = ua;
            *(uint4*)&Bs[bk][bn4] = ub;
        }
        __syncthreads();

        if (k0 + 32 < EE) {
#pragma unroll
            for (int i = 0; i < 4; i++) {
                const int idx = i * 256 + tid;
                const int am  = idx >> 3, ak4 = (idx & 7) << 2;
                const int bk  = idx >> 5, bn4 = (idx & 31) << 2;
                pa[i] = *(const float4*)&A[(size_t)(m0 + am) * EE + k0 + 32 + ak4];
                pb[i] = *(const float4*)&Bw[(size_t)(k0 + 32 + bk) * NDIM + n0 + bn4];
            }
        }

#pragma unroll
        for (int kk = 0; kk < 32; kk += 8) {
            uint32_t af[2][4], bf[8][2];
#pragma unroll
            for (int mt = 0; mt < 2; mt++) {
                const int row = wm * 32 + mt * 16 + lq;
                af[mt][0] = As[row][kk + lr];
                af[mt][1] = As[row + 8][kk + lr];
                af[mt][2] = As[row][kk + lr + 4];
                af[mt][3] = As[row + 8][kk + lr + 4];
            }
#pragma unroll
            for (int nt = 0; nt < 8; nt++) {
                const int col = wn * 64 + nt * 8 + lq;
                bf[nt][0] = Bs[kk + lr][col];
                bf[nt][1] = Bs[kk + lr + 4][col];
            }
#pragma unroll
            for (int mt = 0; mt < 2; mt++)
#pragma unroll
                for (int nt = 0; nt < 8; nt++)
                    mma_tf32(acc[mt][nt], af[mt], bf[nt]);
        }
        __syncthreads();
    }

#pragma unroll
    for (int mt = 0; mt < 2; mt++) {
        const int mA = m0 + wm * 32 + mt * 16 + lq;
        const int mB = mA + 8;
#pragma unroll
        for (int nt = 0; nt < 8; nt++) {
            const int n  = n0 + wn * 64 + nt * 8 + 2 * lr;
            const float bs0 = bias[n], bs1 = bias[n + 1];
            float2 vA = make_float2(acc[mt][nt][0] + bs0, acc[mt][nt][1] + bs1);
            float2 vB = make_float2(acc[mt][nt][2] + bs0, acc[mt][nt][3] + bs1);
            if (EPI == 0) {
                *(float2*)&out0[(size_t)mA * NDIM + n] = vA;
                *(float2*)&out0[(size_t)mB * NDIM + n] = vB;
            } else {
                const int seg = n >> 10;
                const int c   = n & 1023;
                const int h   = c >> 6;
                const int d   = c & 63;
                float* dst = (seg == 0) ? out0 : ((seg == 1) ? out1 : out2);
                const int bA = mA >> 11, sA = mA & 2047;
                const int bB = mB >> 11, sB = mB & 2047;
                *(float2*)&dst[(((size_t)(bA * HH) + h) * SS + sA) * DD + d] = vA;
                *(float2*)&dst[(((size_t)(bB * HH) + h) * SS + sB) * DD + d] = vB;
            }
        }
    }
}

// ---------------------------------------------------------------------------
// tf32 tensor-core flash attention, causal.
// Block = 64 queries (4 warps x 16 rows), K-tile = 64 keys, D = 64.
// Ks [key][dim] stride 68 (conflict-free score-B and P-A frags).
// Vs [key][dim] stride 72 (conflict-free PV-B frags).
// P tile reuses the Ks smem region after scores are consumed.
// ---------------------------------------------------------------------------
__global__ __launch_bounds__(128) void attn_mma_kernel(
    const float* __restrict__ Q, const float* __restrict__ K,
    const float* __restrict__ V, float* __restrict__ O)
{
    __shared__ uint32_t Ks[64][68];
    __shared__ uint32_t Vs[64][72];

    const int tid  = threadIdx.x;
    const int lane = tid & 31;
    const int warp = tid >> 5;
    const int lq   = lane >> 2;
    const int lr   = lane & 3;
    const int qt = blockIdx.x, h = blockIdx.y, b = blockIdx.z;

    const size_t bho = (size_t)(b * HH + h) * SS * DD;
    const float* Qb = Q + bho;
    const float* Kb = K + bho;
    const float* Vb = V + bho;

    const int q0  = qt * 64 + warp * 16;
    const int qg0 = q0 + lq;        // row A (acc c0,c1)
    const int qg1 = q0 + lq + 8;    // row B (acc c2,c3)

    // Q fragments, pre-scaled by 1/sqrt(64)=0.125, tf32
    uint32_t qa[8][4];
#pragma unroll
    for (int kk8 = 0; kk8 < 8; kk8++) {
        const int d0 = kk8 * 8;
        qa[kk8][0] = f2tf32(Qb[(size_t)qg0 * DD + d0 + lr]     * 0.125f);
        qa[kk8][1] = f2tf32(Qb[(size_t)qg1 * DD + d0 + lr]     * 0.125f);
        qa[kk8][2] = f2tf32(Qb[(size_t)qg0 * DD + d0 + lr + 4] * 0.125f);
        qa[kk8][3] = f2tf32(Qb[(size_t)qg1 * DD + d0 + lr + 4] * 0.125f);
    }

    float oacc[8][4];
#pragma unroll
    for (int nt = 0; nt < 8; nt++)
#pragma unroll
        for (int t = 0; t < 4; t++) oacc[nt][t] = 0.f;
    float m0 = -1e30f, m1 = -1e30f, l0 = 0.f, l1 = 0.f;

    for (int kt = 0; kt <= qt; kt++) {
        __syncthreads();   // prior tile's PV reads of Ks(P)/Vs are done
        // load K/V tile (64x64 floats each) with tf32 convert
#pragma unroll
        for (int i = 0; i < 8; i++) {
            const int idx = i * 128 + tid;        // 0..1023 float4 slots
            const int row = idx >> 4;
            const int c4  = (idx & 15) << 2;
            float4 kv = *(const float4*)&Kb[(size_t)(kt * 64 + row) * DD + c4];
            float4 vv = *(const float4*)&Vb[(size_t)(kt * 64 + row) * DD + c4];
            Ks[row][c4+0] = f2tf32(kv.x); Ks[row][c4+1] = f2tf32(kv.y);
            Ks[row][c4+2] = f2tf32(kv.z); Ks[row][c4+3] = f2tf32(kv.w);
            Vs[row][c4+0] = f2tf32(vv.x); Vs[row][c4+1] = f2tf32(vv.y);
            Vs[row][c4+2] = f2tf32(vv.z); Vs[row][c4+3] = f2tf32(vv.w);
        }
        __syncthreads();

        // --- scores: S = (Q*scale) . K^T ---
        float sacc[8][4];
#pragma unroll
        for (int nt = 0; nt < 8; nt++)
#pragma unroll
            for (int t = 0; t < 4; t++) sacc[nt][t] = 0.f;
#pragma unroll
        for (int kk8 = 0; kk8 < 8; kk8++) {
#pragma unroll
            for (int nt = 0; nt < 8; nt++) {
                uint32_t bf[2];
                bf[0] = Ks[nt * 8 + lq][kk8 * 8 + lr];
                bf[1] = Ks[nt * 8 + lq][kk8 * 8 + lr + 4];
                mma_tf32(sacc[nt], qa[kk8], bf);
            }
        }

        // --- causal mask + row max ---
        float rmax0 = m0, rmax1 = m1;
#pragma unroll
        for (int nt = 0; nt < 8; nt++) {
            const int gk = kt * 64 + nt * 8 + 2 * lr;
            if (gk     > qg0) sacc[nt][0] = -1e30f;
            if (gk + 1 > qg0) sacc[nt][1] = -1e30f;
            if (gk     > qg1) sacc[nt][2] = -1e30f;
            if (gk + 1 > qg1) sacc[nt][3] = -1e30f;
            rmax0 = fmaxf(rmax0, fmaxf(sacc[nt][0], sacc[nt][1]));
            rmax1 = fmaxf(rmax1, fmaxf(sacc[nt][2], sacc[nt][3]));
        }
        rmax0 = fmaxf(rmax0, __shfl_xor_sync(0xffffffffu, rmax0, 1));
        rmax0 = fmaxf(rmax0, __shfl_xor_sync(0xffffffffu, rmax0, 2));
        rmax1 = fmaxf(rmax1, __shfl_xor_sync(0xffffffffu, rmax1, 1));
        rmax1 = fmaxf(rmax1, __shfl_xor_sync(0xffffffffu, rmax1, 2));

        const float a0 = __expf(m0 - rmax0);
        const float a1 = __expf(m1 - rmax1);
        m0 = rmax0; m1 = rmax1;

        float ls0 = 0.f, ls1 = 0.f;
#pragma unroll
        for (int nt = 0; nt < 8; nt++) {
            sacc[nt][0] = __expf(sacc[nt][0] - m0);
            sacc[nt][1] = __expf(sacc[nt][1] - m0);
            sacc[nt][2] = __expf(sacc[nt][2] - m1);
            sacc[nt][3] = __expf(sacc[nt][3] - m1);
            ls0 += sacc[nt][0] + sacc[nt][1];
            ls1 += sacc[nt][2] + sacc[nt][3];
        }
        ls0 += __shfl_xor_sync(0xffffffffu, ls0, 1);
        ls0 += __shfl_xor_sync(0xffffffffu, ls0, 2);
        ls1 += __shfl_xor_sync(0xffffffffu, ls1, 1);
        ls1 += __shfl_xor_sync(0xffffffffu, ls1, 2);
        l0 = l0 * a0 + ls0;
        l1 = l1 * a1 + ls1;

        // rescale O accumulators
#pragma unroll
        for (int nt = 0; nt < 8; nt++) {
            oacc[nt][0] *= a0; oacc[nt][1] *= a0;
            oacc[nt][2] *= a1; oacc[nt][3] *= a1;
        }

        __syncthreads();   // all warps done reading Ks -> safe to overwrite with P

        // write P (tf32) into this warp's 16 rows of the Ks region, stride 68
        uint32_t* Ps = &Ks[warp * 16][0];
#pragma unroll
        for (int nt = 0; nt < 8; nt++) {
            uint2 p0 = make_uint2(f2tf32(sacc[nt][0]), f2tf32(sacc[nt][1]));
            uint2 p1 = make_uint2(f2tf32(sacc[nt][2]), f2tf32(sacc[nt][3]));
            *(uint2*)&Ps[lq * 68 + nt * 8 + 2 * lr]       = p0;
            *(uint2*)&Ps[(lq + 8) * 68 + nt * 8 + 2 * lr] = p1;
        }
        __syncwarp();

        // --- O += P . V ---
#pragma unroll
        for (int kk8 = 0; kk8 < 8; kk8++) {
            uint32_t af[4];
            af[0] = Ps[lq * 68 + kk8 * 8 + lr];
            af[1] = Ps[(lq + 8) * 68 + kk8 * 8 + lr];
            af[2] = Ps[lq * 68 + kk8 * 8 + lr + 4];
            af[3] = Ps[(lq + 8) * 68 + kk8 * 8 + lr + 4];
#pragma unroll
            for (int nt = 0; nt < 8; nt++) {
                uint32_t bf[2];
                bf[0] = Vs[kk8 * 8 + lr][nt * 8 + lq];
                bf[1] = Vs[kk8 * 8 + lr + 4][nt * 8 + lq];
                mma_tf32(oacc[nt], af, bf);
            }
        }
    }

    // epilogue: normalize, write [B,S,E] row-major for the proj GEMM
    const float inv0 = 1.f / l0;
    const float inv1 = 1.f / l1;
    const size_t r0 = (size_t)(b * SS + qg0) * EE + h * 64;
    const size_t r1 = (size_t)(b * SS + qg1) * EE + h * 64;
#pragma unroll
    for (int nt = 0; nt < 8; nt++) {
        float2 v0 = make_float2(oacc[nt][0] * inv0, oacc[nt][1] * inv0);
        float2 v1 = make_float2(oacc[nt][2] * inv1, oacc[nt][3] * inv1);
        *(float2*)&O[r0 + nt * 8 + 2 * lr] = v0;
        *(float2*)&O[r1 + nt * 8 + 2 * lr] = v1;
    }
}

// ---------------------------------------------------------------------------
extern "C" void kernel_launch(void* const* d_in, const int* in_sizes, int n_in,
                              void* d_out, int out_size)
{
    const float* x      = (const float*)d_in[0];
    const float* qkv_w  = (const float*)d_in[1];
    const float* qkv_b  = (const float*)d_in[2];
    const float* proj_w = (const float*)d_in[3];
    const float* proj_b = (const float*)d_in[4];
    float* out = (float*)d_out;

    float *qbuf, *attnbuf, *kscr, *vscr;
    cudaGetSymbolAddress((void**)&qbuf,    g_q);
    cudaGetSymbolAddress((void**)&attnbuf, g_attn);
    cudaGetSymbolAddress((void**)&kscr,    g_kscr);
    cudaGetSymbolAddress((void**)&vscr,    g_vscr);

    const bool kv_in_out = (out_size >= 3*OUTN);
    float* kdst = kv_in_out ? (out + OUTN)   : kscr;
    float* vdst = kv_in_out ? (out + 2*OUTN) : vscr;

    mma_gemm_kernel<N3, 1><<<dim3(N3/128, MM/128), 256>>>(x, qkv_w, qkv_b,
                                                          qbuf, kdst, vdst);
    attn_mma_kernel<<<dim3(SS/64, HH, BB), 128>>>(qbuf, kdst, vdst, attnbuf);
    mma_gemm_kernel<EE, 0><<<dim3(EE/128, MM/128), 256>>>(attnbuf, proj_w, proj_b,
                                                          out, nullptr, nullptr);
}